// round 14
// baseline (speedup 1.0000x reference)
#include <cuda_runtime.h>

#define BATCH 512
#define SEQ   512
#define VOCAB 1000
#define EMB   100
#define UNITS 64

typedef unsigned long long ull;

// Scratch: projected embedding table (emb @ Wxh + b), 1000 x 64 fp32 = 256 KB.
__device__ float g_embproj[VOCAB * UNITS];
// Grid barrier state (zero-init at module load; reset by block 0 each launch).
__device__ unsigned g_cnt  = 0;
__device__ unsigned g_flag = 0;

// ---- packed f32x2 helpers (Blackwell 2xFP32 path, PTX-only) ----
__device__ __forceinline__ ull fma2(ull a, ull b, ull c) {
    ull d;
    asm("fma.rn.f32x2 %0, %1, %2, %3;" : "=l"(d) : "l"(a), "l"(b), "l"(c));
    return d;
}
__device__ __forceinline__ ull mul2(ull a, ull b) {
    ull d;
    asm("mul.rn.f32x2 %0, %1, %2;" : "=l"(d) : "l"(a), "l"(b));
    return d;
}
__device__ __forceinline__ ull add2(ull a, ull b) {
    ull d;
    asm("add.rn.f32x2 %0, %1, %2;" : "=l"(d) : "l"(a), "l"(b));
    return d;
}
__device__ __forceinline__ ull pack2(float lo, float hi) {
    ull d;
    asm("mov.b64 %0, {%1, %2};"
        : "=l"(d) : "r"(__float_as_uint(lo)), "r"(__float_as_uint(hi)));
    return d;
}
__device__ __forceinline__ void unpack2(ull v, float& lo, float& hi) {
    unsigned a, b;
    asm("mov.b64 {%0, %1}, %2;" : "=r"(a), "=r"(b) : "l"(v));
    lo = __uint_as_float(a);
    hi = __uint_as_float(b);
}

// Single-MUFU tanh (sm_75+).
__device__ __forceinline__ float tanh_mufu(float x) {
    float y;
    asm("tanh.approx.f32 %0, %1;" : "=f"(y) : "f"(x));
    return y;
}

// ---------------------------------------------------------------------------
// Fused kernel.
// Phase 1: blocks 0..124 compute 8 vocab rows of embproj each; Wxh staged in
//          smem (LDS, conflict-free), 4 rows interleaved with float4 emb
//          loads for MLP.
// Phase 2: device-wide flag barrier (all 128 blocks co-resident; grid<=SMs).
//          Token staging + weight packing hoisted into the wait window.
// Phase 3: proven R9 RNN body (one warp per row, k-pair packed FFMA2).
// ---------------------------------------------------------------------------
__global__ __launch_bounds__(128, 1)
void k_rnn(const int*   __restrict__ tokens,
           const float* __restrict__ emb,
           const float* __restrict__ Wxh,
           const float* __restrict__ bias,
           const float* __restrict__ Whh,
           const float* __restrict__ Wout,
           const float* __restrict__ bout,
           float*       __restrict__ out) {
    __shared__ __align__(16) float hs[4][UNITS];   // h per warp
    __shared__ __align__(8) int tok[4][SEQ + 4];   // token*UNITS, padded
    __shared__ __align__(16) float wxs[EMB * UNITS];  // staged Wxh, 25.6 KB

    const int w    = threadIdx.x >> 5;
    const int lane = threadIdx.x & 31;
    const int row  = blockIdx.x * 4 + w;

    // ---- Phase 1: embproj slice ----
    // Stage Wxh into smem (coalesced float4; 1600 not divisible by 128 ->
    // the loop condition itself is the bounds guard).
    for (int i = threadIdx.x; i < EMB * UNITS / 4; i += 128)
        ((float4*)wxs)[i] = ((const float4*)Wxh)[i];
    __syncthreads();

    if (blockIdx.x < VOCAB / 8) {   // 125 blocks cover 1000 vocab rows
        const int u  = threadIdx.x & 63;
        const int vg = threadIdx.x >> 6;            // 0..1
        const int vbase = blockIdx.x * 8 + vg;      // rows vbase+0,2,4,6
        const float bu = bias[u];
        const float* e0 = emb + (vbase + 0) * EMB;
        const float* e1 = emb + (vbase + 2) * EMB;
        const float* e2 = emb + (vbase + 4) * EMB;
        const float* e3 = emb + (vbase + 6) * EMB;
        float s0 = bu, s1 = bu, s2 = bu, s3 = bu;
        float t0 = 0.f, t1 = 0.f, t2 = 0.f, t3 = 0.f;
#pragma unroll 5
        for (int d = 0; d < EMB; d += 4) {
            float4 a0 = __ldg((const float4*)(e0 + d));
            float4 a1 = __ldg((const float4*)(e1 + d));
            float4 a2 = __ldg((const float4*)(e2 + d));
            float4 a3 = __ldg((const float4*)(e3 + d));
            float w0 = wxs[(d + 0) * UNITS + u];
            float w1 = wxs[(d + 1) * UNITS + u];
            float w2 = wxs[(d + 2) * UNITS + u];
            float w3 = wxs[(d + 3) * UNITS + u];
            s0 = fmaf(a0.x, w0, s0);  t0 = fmaf(a0.y, w1, t0);
            s0 = fmaf(a0.z, w2, s0);  t0 = fmaf(a0.w, w3, t0);
            s1 = fmaf(a1.x, w0, s1);  t1 = fmaf(a1.y, w1, t1);
            s1 = fmaf(a1.z, w2, s1);  t1 = fmaf(a1.w, w3, t1);
            s2 = fmaf(a2.x, w0, s2);  t2 = fmaf(a2.y, w1, t2);
            s2 = fmaf(a2.z, w2, s2);  t2 = fmaf(a2.w, w3, t2);
            s3 = fmaf(a3.x, w0, s3);  t3 = fmaf(a3.y, w1, t3);
            s3 = fmaf(a3.z, w2, s3);  t3 = fmaf(a3.w, w3, t3);
        }
        g_embproj[(vbase + 0) * UNITS + u] = s0 + t0;
        g_embproj[(vbase + 2) * UNITS + u] = s1 + t1;
        g_embproj[(vbase + 4) * UNITS + u] = s2 + t2;
        g_embproj[(vbase + 6) * UNITS + u] = s3 + t3;
    }
    __threadfence();
    __syncthreads();
    if (threadIdx.x == 0) {
        unsigned t = atomicAdd(&g_cnt, 1u);
        if (t == (unsigned)(gridDim.x - 1)) atomicExch(&g_flag, 1u);
    }

    // ---- Overlap the barrier wait with independent prologue work ----

    // Stage tokens premultiplied by UNITS (coalesced int4), pad 2 entries.
    {
        const int4* src = (const int4*)(tokens + row * SEQ);
        int4* dst = (int4*)tok[w];
#pragma unroll
        for (int i = 0; i < 4; ++i) {
            int4 v = src[lane + 32 * i];
            v.x *= UNITS; v.y *= UNITS; v.z *= UNITS; v.w *= UNITS;
            dst[lane + 32 * i] = v;
        }
        if (lane == 0) {
            int last = tok[w][SEQ - 1];
            tok[w][SEQ]     = last;
            tok[w][SEQ + 1] = last;
        }
    }

    // Weight registers, k-pair packed:
    //   wq0[j] = (W[2j][u0], W[2j+1][u0]),  wq1[j] = (W[2j][u1], W[2j+1][u1])
    ull wq0[UNITS / 2], wq1[UNITS / 2];
#pragma unroll
    for (int j = 0; j < UNITS / 2; ++j) {
        float2 we = *(const float2*)(Whh + (2 * j)     * UNITS + 2 * lane);
        float2 wo = *(const float2*)(Whh + (2 * j + 1) * UNITS + 2 * lane);
        wq0[j] = pack2(we.x, wo.x);
        wq1[j] = pack2(we.y, wo.y);
    }

    // h0 = 0
    *(float2*)(hs[w] + 2 * lane) = make_float2(0.f, 0.f);

    // ---- Complete the grid barrier ----
    if (threadIdx.x == 0) {
        while (atomicAdd(&g_flag, 0u) == 0u) __nanosleep(64);
        __threadfence();
    }
    __syncthreads();

    const float* epl = g_embproj + 2 * lane;   // lane-fixed base
    float* hrow = hs[w];
    const ull* hp = (const ull*)hrow;          // packed (h_2j, h_2j+1) pairs

    float h0v = 0.0f, h1v = 0.0f;

    // Double-buffered gather, prefetch distance 2.
    float2 xa = __ldg((const float2*)(epl + tok[w][0]));
    float2 xb = __ldg((const float2*)(epl + tok[w][1]));

    // One recurrence step (proven R9 body). Pair-group 0 initializes the 2
    // accumulators per unit; groups 1..7 accumulate. 1 add2 tail, MUFU tanh.
#define RNN_BODY(xcur)                                                        \
    {                                                                         \
        ull A0, A1, B0, B1;                                                   \
        {                                                                     \
            ulonglong2 q01 = *(const ulonglong2*)(hp);                        \
            ulonglong2 q23 = *(const ulonglong2*)(hp + 2);                    \
            A0 = fma2(q01.x, wq0[0], pack2((xcur).x, 0.f));                   \
            B0 = fma2(q01.x, wq1[0], pack2((xcur).y, 0.f));                   \
            A1 = mul2(q01.y, wq0[1]);  B1 = mul2(q01.y, wq1[1]);              \
            A0 = fma2(q23.x, wq0[2], A0);  B0 = fma2(q23.x, wq1[2], B0);      \
            A1 = fma2(q23.y, wq0[3], A1);  B1 = fma2(q23.y, wq1[3], B1);      \
        }                                                                     \
        _Pragma("unroll")                                                     \
        for (int g = 1; g < 8; ++g) {                                         \
            ulonglong2 q01 = *(const ulonglong2*)(hp + 4 * g);                \
            ulonglong2 q23 = *(const ulonglong2*)(hp + 4 * g + 2);            \
            A0 = fma2(q01.x, wq0[4 * g + 0], A0);                             \
            B0 = fma2(q01.x, wq1[4 * g + 0], B0);                             \
            A1 = fma2(q01.y, wq0[4 * g + 1], A1);                             \
            B1 = fma2(q01.y, wq1[4 * g + 1], B1);                             \
            A0 = fma2(q23.x, wq0[4 * g + 2], A0);                             \
            B0 = fma2(q23.x, wq1[4 * g + 2], B0);                             \
            A1 = fma2(q23.y, wq0[4 * g + 3], A1);                             \
            B1 = fma2(q23.y, wq1[4 * g + 3], B1);                             \
        }                                                                     \
        ull sa = add2(A0, A1);                                                \
        ull sb = add2(B0, B1);                                                \
        float sa0, sa1, sb0, sb1;                                             \
        unpack2(sa, sa0, sa1);                                                \
        unpack2(sb, sb0, sb1);                                                \
        h0v = tanh_mufu(sa0 + sa1);                                           \
        h1v = tanh_mufu(sb0 + sb1);                                           \
        *(float2*)(hrow + 2 * lane) = make_float2(h0v, h1v);                  \
        asm volatile("" ::: "memory");                                        \
    }

    for (int t = 0; t < SEQ; t += 2) {
        int2 tp = *(const int2*)(tok[w] + t + 2);   // tokens t+2, t+3
        float2 xn0 = __ldg((const float2*)(epl + tp.x));
        float2 xn1 = __ldg((const float2*)(epl + tp.y));

        RNN_BODY(xa);
        RNN_BODY(xb);

        xa = xn0;
        xb = xn1;
    }
#undef RNN_BODY

    // Epilogue: sigmoid(hT @ Wout + bout)
    float2 wo = *(const float2*)(Wout + 2 * lane);
    float part = h0v * wo.x + h1v * wo.y;
#pragma unroll
    for (int o = 16; o; o >>= 1)
        part += __shfl_xor_sync(0xffffffffu, part, o);
    if (lane == 0) {
        float z = part + bout[0];
        float e, r;
        asm("ex2.approx.f32 %0, %1;" : "=f"(e) : "f"(-z * 1.4426950408889634f));
        asm("rcp.approx.f32 %0, %1;" : "=f"(r) : "f"(1.0f + e));
        out[row] = r;
    }

    // Reset barrier state for the next (graph-replayed) launch. Safe: every
    // block passed the poll ~150k cycles before block 0 reaches this point.
    if (blockIdx.x == 0 && threadIdx.x == 0) {
        atomicExch(&g_flag, 0u);
        atomicExch(&g_cnt, 0u);
    }
}

extern "C" void kernel_launch(void* const* d_in, const int* in_sizes, int n_in,
                              void* d_out, int out_size) {
    const int*   tokens = (const int*)d_in[0];
    const float* emb    = (const float*)d_in[1];
    const float* Wxh    = (const float*)d_in[2];
    const float* Whh    = (const float*)d_in[3];
    const float* b      = (const float*)d_in[4];
    const float* Wout   = (const float*)d_in[5];
    const float* bout   = (const float*)d_in[6];
    float* out = (float*)d_out;

    k_rnn<<<BATCH / 4, 128>>>(tokens, emb, Wxh, b, Whh, Wout, bout, out);
}

// round 15
// speedup vs baseline: 1.0276x; 1.0276x over previous
#include <cuda_runtime.h>

#define BATCH 512
#define SEQ   512
#define VOCAB 1000
#define EMB   100
#define UNITS 64

typedef unsigned long long ull;

// Scratch: projected embedding table (emb @ Wxh + b), 1000 x 64 fp32 = 256 KB.
__device__ float g_embproj[VOCAB * UNITS];

// ---- packed f32x2 helpers (Blackwell 2xFP32 path, PTX-only) ----
__device__ __forceinline__ ull fma2(ull a, ull b, ull c) {
    ull d;
    asm("fma.rn.f32x2 %0, %1, %2, %3;" : "=l"(d) : "l"(a), "l"(b), "l"(c));
    return d;
}
__device__ __forceinline__ ull mul2(ull a, ull b) {
    ull d;
    asm("mul.rn.f32x2 %0, %1, %2;" : "=l"(d) : "l"(a), "l"(b));
    return d;
}
__device__ __forceinline__ ull add2(ull a, ull b) {
    ull d;
    asm("add.rn.f32x2 %0, %1, %2;" : "=l"(d) : "l"(a), "l"(b));
    return d;
}
__device__ __forceinline__ ull pack2(float lo, float hi) {
    ull d;
    asm("mov.b64 %0, {%1, %2};"
        : "=l"(d) : "r"(__float_as_uint(lo)), "r"(__float_as_uint(hi)));
    return d;
}
__device__ __forceinline__ void unpack2(ull v, float& lo, float& hi) {
    unsigned a, b;
    asm("mov.b64 {%0, %1}, %2;" : "=r"(a), "=r"(b) : "l"(v));
    lo = __uint_as_float(a);
    hi = __uint_as_float(b);
}

// Single-MUFU tanh (sm_75+).
__device__ __forceinline__ float tanh_mufu(float x) {
    float y;
    asm("tanh.approx.f32 %0, %1;" : "=f"(y) : "f"(x));
    return y;
}

// ---------------------------------------------------------------------------
// Prologue: embproj[v][u] = sum_d emb[v][d] * Wxh[d][u] + b[u]
// 512-thread blocks, 8 vocab rows per block (proven R9 config). Signals PDL
// completion right after its stores so the dependent k_rnn can begin its
// independent prologue while this kernel drains.
// ---------------------------------------------------------------------------
__global__ __launch_bounds__(512)
void k_embproj(const float* __restrict__ emb,
               const float* __restrict__ Wxh,
               const float* __restrict__ bias) {
    int v = blockIdx.x * 8 + (threadIdx.x >> 6);
    int u = threadIdx.x & 63;
    if (v < VOCAB) {
        const float* er = emb + v * EMB;
        float a0 = bias[u], a1 = 0.f, a2 = 0.f, a3 = 0.f;
#pragma unroll
        for (int d = 0; d < EMB; d += 4) {
            a0 = fmaf(__ldg(er + d),     __ldg(Wxh + (d)     * UNITS + u), a0);
            a1 = fmaf(__ldg(er + d + 1), __ldg(Wxh + (d + 1) * UNITS + u), a1);
            a2 = fmaf(__ldg(er + d + 2), __ldg(Wxh + (d + 2) * UNITS + u), a2);
            a3 = fmaf(__ldg(er + d + 3), __ldg(Wxh + (d + 3) * UNITS + u), a3);
        }
        g_embproj[v * UNITS + u] = (a0 + a1) + (a2 + a3);
    }
#if __CUDA_ARCH__ >= 900
    cudaTriggerProgrammaticLaunchCompletion();
#endif
}

// ---------------------------------------------------------------------------
// Main: one warp per batch row (proven R9 body). Lane l owns units 2l, 2l+1.
// Launched with programmatic stream serialization: the prologue (token
// staging, weight packing, h0) overlaps k_embproj's tail; the grid-dependency
// sync lands just before the first g_embproj gather.
// ---------------------------------------------------------------------------
__global__ __launch_bounds__(128, 1)
void k_rnn(const int*   __restrict__ tokens,
           const float* __restrict__ Whh,
           const float* __restrict__ Wout,
           const float* __restrict__ bout,
           float*       __restrict__ out) {
    __shared__ __align__(16) float hs[4][UNITS];   // h per warp
    __shared__ __align__(8) int tok[4][SEQ + 4];   // token*UNITS, padded

    const int w    = threadIdx.x >> 5;
    const int lane = threadIdx.x & 31;
    const int row  = blockIdx.x * 4 + w;

    // Stage tokens premultiplied by UNITS (coalesced int4), pad 2 entries.
    {
        const int4* src = (const int4*)(tokens + row * SEQ);
        int4* dst = (int4*)tok[w];
#pragma unroll
        for (int i = 0; i < 4; ++i) {
            int4 v = src[lane + 32 * i];
            v.x *= UNITS; v.y *= UNITS; v.z *= UNITS; v.w *= UNITS;
            dst[lane + 32 * i] = v;
        }
        if (lane == 0) {
            int last = tok[w][SEQ - 1];
            tok[w][SEQ]     = last;
            tok[w][SEQ + 1] = last;
        }
    }

    // Weight registers, k-pair packed:
    //   wq0[j] = (W[2j][u0], W[2j+1][u0]),  wq1[j] = (W[2j][u1], W[2j+1][u1])
    ull wq0[UNITS / 2], wq1[UNITS / 2];
#pragma unroll
    for (int j = 0; j < UNITS / 2; ++j) {
        float2 we = *(const float2*)(Whh + (2 * j)     * UNITS + 2 * lane);
        float2 wo = *(const float2*)(Whh + (2 * j + 1) * UNITS + 2 * lane);
        wq0[j] = pack2(we.x, wo.x);
        wq1[j] = pack2(we.y, wo.y);
    }

    // h0 = 0
    *(float2*)(hs[w] + 2 * lane) = make_float2(0.f, 0.f);
    __syncwarp();

    // Wait for k_embproj's writes to be visible before the first gather.
#if __CUDA_ARCH__ >= 900
    cudaGridDependencySynchronize();
#endif

    const float* epl = g_embproj + 2 * lane;   // lane-fixed base
    float* hrow = hs[w];
    const ull* hp = (const ull*)hrow;          // packed (h_2j, h_2j+1) pairs

    float h0v = 0.0f, h1v = 0.0f;

    // Double-buffered gather, prefetch distance 2.
    float2 xa = __ldg((const float2*)(epl + tok[w][0]));
    float2 xb = __ldg((const float2*)(epl + tok[w][1]));

    // One recurrence step (proven R9 body). Pair-group 0 initializes the 2
    // accumulators per unit; groups 1..7 accumulate. 1 add2 tail, MUFU tanh.
#define RNN_BODY(xcur)                                                        \
    {                                                                         \
        ull A0, A1, B0, B1;                                                   \
        {                                                                     \
            ulonglong2 q01 = *(const ulonglong2*)(hp);                        \
            ulonglong2 q23 = *(const ulonglong2*)(hp + 2);                    \
            A0 = fma2(q01.x, wq0[0], pack2((xcur).x, 0.f));                   \
            B0 = fma2(q01.x, wq1[0], pack2((xcur).y, 0.f));                   \
            A1 = mul2(q01.y, wq0[1]);  B1 = mul2(q01.y, wq1[1]);              \
            A0 = fma2(q23.x, wq0[2], A0);  B0 = fma2(q23.x, wq1[2], B0);      \
            A1 = fma2(q23.y, wq0[3], A1);  B1 = fma2(q23.y, wq1[3], B1);      \
        }                                                                     \
        _Pragma("unroll")                                                     \
        for (int g = 1; g < 8; ++g) {                                         \
            ulonglong2 q01 = *(const ulonglong2*)(hp + 4 * g);                \
            ulonglong2 q23 = *(const ulonglong2*)(hp + 4 * g + 2);            \
            A0 = fma2(q01.x, wq0[4 * g + 0], A0);                             \
            B0 = fma2(q01.x, wq1[4 * g + 0], B0);                             \
            A1 = fma2(q01.y, wq0[4 * g + 1], A1);                             \
            B1 = fma2(q01.y, wq1[4 * g + 1], B1);                             \
            A0 = fma2(q23.x, wq0[4 * g + 2], A0);                             \
            B0 = fma2(q23.x, wq1[4 * g + 2], B0);                             \
            A1 = fma2(q23.y, wq0[4 * g + 3], A1);                             \
            B1 = fma2(q23.y, wq1[4 * g + 3], B1);                             \
        }                                                                     \
        ull sa = add2(A0, A1);                                                \
        ull sb = add2(B0, B1);                                                \
        float sa0, sa1, sb0, sb1;                                             \
        unpack2(sa, sa0, sa1);                                                \
        unpack2(sb, sb0, sb1);                                                \
        h0v = tanh_mufu(sa0 + sa1);                                           \
        h1v = tanh_mufu(sb0 + sb1);                                           \
        *(float2*)(hrow + 2 * lane) = make_float2(h0v, h1v);                  \
        asm volatile("" ::: "memory");                                        \
    }

    for (int t = 0; t < SEQ; t += 2) {
        int2 tp = *(const int2*)(tok[w] + t + 2);   // tokens t+2, t+3
        float2 xn0 = __ldg((const float2*)(epl + tp.x));
        float2 xn1 = __ldg((const float2*)(epl + tp.y));

        RNN_BODY(xa);
        RNN_BODY(xb);

        xa = xn0;
        xb = xn1;
    }
#undef RNN_BODY

    // Epilogue: sigmoid(hT @ Wout + bout)
    float2 wo = *(const float2*)(Wout + 2 * lane);
    float part = h0v * wo.x + h1v * wo.y;
#pragma unroll
    for (int o = 16; o; o >>= 1)
        part += __shfl_xor_sync(0xffffffffu, part, o);
    if (lane == 0) {
        float z = part + bout[0];
        float e, r;
        asm("ex2.approx.f32 %0, %1;" : "=f"(e) : "f"(-z * 1.4426950408889634f));
        asm("rcp.approx.f32 %0, %1;" : "=f"(r) : "f"(1.0f + e));
        out[row] = r;
    }
}

extern "C" void kernel_launch(void* const* d_in, const int* in_sizes, int n_in,
                              void* d_out, int out_size) {
    const int*   tokens = (const int*)d_in[0];
    const float* emb    = (const float*)d_in[1];
    const float* Wxh    = (const float*)d_in[2];
    const float* Whh    = (const float*)d_in[3];
    const float* b      = (const float*)d_in[4];
    const float* Wout   = (const float*)d_in[5];
    const float* bout   = (const float*)d_in[6];
    float* out = (float*)d_out;

    // Primary: embproj (triggers programmatic completion after stores).
    k_embproj<<<(VOCAB + 7) / 8, 512>>>(emb, Wxh, b);

    // Secondary: RNN with programmatic dependent launch — its prologue
    // overlaps embproj's tail; cudaGridDependencySynchronize() guards the
    // first gather.
    cudaLaunchConfig_t cfg = {};
    cfg.gridDim  = dim3(BATCH / 4, 1, 1);
    cfg.blockDim = dim3(128, 1, 1);
    cfg.dynamicSmemBytes = 0;
    cfg.stream = 0;
    cudaLaunchAttribute attrs[1];
    attrs[0].id = cudaLaunchAttributeProgrammaticStreamSerialization;
    attrs[0].val.programmaticStreamSerializationAllowed = 1;
    cfg.attrs = attrs;
    cfg.numAttrs = 1;
    cudaLaunchKernelEx(&cfg, k_rnn, tokens, Whh, Wout, bout, out);
}